// round 6
// baseline (speedup 1.0000x reference)
#include <cuda_runtime.h>
#include <cuda_bf16.h>
#include <cstdint>
#include <math.h>

#define T_TOK 2048
#define DIM 1024
#define HID 4096
#define NE 8

#define BM 64
#define BN 64
#define BK 32
#define BKP 40  // padded k-stride (bf16): 80B rows -> conflict-free ldmatrix (r*20 mod 32 disjoint)

// -------- scratch (device globals; no allocation allowed) --------
__device__ int g_cnt[NE];
__device__ int g_list[NE * T_TOK];
__device__ float g_wpair[2 * T_TOK];
__device__ __align__(256) __nv_bfloat16 g_hh[(size_t)2 * T_TOK * HID];  // h hi, 32MB
__device__ __align__(256) __nv_bfloat16 g_hl[(size_t)2 * T_TOK * HID];  // h lo, 32MB
__device__ __align__(256) float g_ye[(size_t)2 * T_TOK * DIM];          // 16MB

// ---------------- helpers ----------------
__device__ __forceinline__ void mma16816(float c[4], const uint32_t a[4], uint32_t b0,
                                         uint32_t b1) {
  asm volatile(
      "mma.sync.aligned.m16n8k16.row.col.f32.bf16.bf16.f32 "
      "{%0,%1,%2,%3}, {%4,%5,%6,%7}, {%8,%9}, {%0,%1,%2,%3};\n"
      : "+f"(c[0]), "+f"(c[1]), "+f"(c[2]), "+f"(c[3])
      : "r"(a[0]), "r"(a[1]), "r"(a[2]), "r"(a[3]), "r"(b0), "r"(b1));
}

__device__ __forceinline__ void ldsm4(uint32_t r[4], const __nv_bfloat16* p) {
  uint32_t a = (uint32_t)__cvta_generic_to_shared(p);
  asm volatile("ldmatrix.sync.aligned.m8n8.x4.shared.b16 {%0,%1,%2,%3}, [%4];"
               : "=r"(r[0]), "=r"(r[1]), "=r"(r[2]), "=r"(r[3])
               : "r"(a));
}

// pack (x0,x1) -> bf16x2 hi word + bf16x2 residual word
__device__ __forceinline__ void split2(float x0, float x1, uint32_t& hi, uint32_t& lo) {
  asm("cvt.rn.bf16x2.f32 %0, %1, %2;" : "=r"(hi) : "f"(x1), "f"(x0));
  float h0 = __uint_as_float(hi << 16);
  float h1 = __uint_as_float(hi & 0xffff0000u);
  float l0 = x0 - h0, l1 = x1 - h1;
  asm("cvt.rn.bf16x2.f32 %0, %1, %2;" : "=r"(lo) : "f"(l1), "f"(l0));
}

__device__ __forceinline__ void split4(float4 v, uint2& hi, uint2& lo) {
  uint32_t h0, l0, h1, l1;
  split2(v.x, v.y, h0, l0);
  split2(v.z, v.w, h1, l1);
  hi = make_uint2(h0, h1);
  lo = make_uint2(l0, l1);
}

// ---------------- small kernels ----------------
__global__ void reset_kernel() {
  if (threadIdx.x < NE) g_cnt[threadIdx.x] = 0;
}

__global__ void gate_kernel(const float* __restrict__ x, const float* __restrict__ gw) {
  int t = blockIdx.x * 4 + (threadIdx.x >> 5);
  int lane = threadIdx.x & 31;
  float p[NE];
#pragma unroll
  for (int e = 0; e < NE; e++) p[e] = 0.f;
  const float* xr = x + (size_t)t * DIM;
  for (int j = lane; j < DIM; j += 32) {
    float xv = xr[j];
#pragma unroll
    for (int e = 0; e < NE; e++) p[e] += xv * gw[e * DIM + j];
  }
#pragma unroll
  for (int off = 16; off > 0; off >>= 1) {
#pragma unroll
    for (int e = 0; e < NE; e++) p[e] += __shfl_xor_sync(0xffffffffu, p[e], off);
  }
  if (lane == 0) {
    int i0 = 0;
    float v0 = p[0];
#pragma unroll
    for (int e = 1; e < NE; e++)
      if (p[e] > v0) { v0 = p[e]; i0 = e; }
    int i1 = -1;
    float v1 = -3.0e38f;
#pragma unroll
    for (int e = 0; e < NE; e++)
      if (e != i0 && p[e] > v1) { v1 = p[e]; i1 = e; }
    float e1 = expf(v1 - v0);
    float s = 1.f + e1;
    float w0 = 1.f / s, w1v = e1 / s;
    int pos = atomicAdd(&g_cnt[i0], 1);
    g_list[i0 * T_TOK + pos] = t * 2;
    g_wpair[t * 2] = w0;
    pos = atomicAdd(&g_cnt[i1], 1);
    g_list[i1 * T_TOK + pos] = t * 2 + 1;
    g_wpair[t * 2 + 1] = w1v;
  }
}

// ---------------- FFN1: h = silu(x w1^T) * (x w3^T), grouped by expert ----------------
__global__ __launch_bounds__(128, 2) void ffn1_kernel(const float* __restrict__ x,
                                                      const float* __restrict__ w1,
                                                      const float* __restrict__ w3) {
  int e = blockIdx.z;
  int ne = g_cnt[e];
  int m0 = blockIdx.y * BM;
  if (m0 >= ne) return;
  int n0 = blockIdx.x * BN;

  __shared__ __align__(16) __nv_bfloat16 sAh[BM][BKP], sAl[BM][BKP];
  __shared__ __align__(16) __nv_bfloat16 sB1h[BN][BKP], sB1l[BN][BKP];
  __shared__ __align__(16) __nv_bfloat16 sB3h[BN][BKP], sB3l[BN][BKP];
  __shared__ int sRow[BM];

  int tid = threadIdx.x;
  int lane = tid & 31, warp = tid >> 5;
  int wm = warp >> 1, wn = warp & 1;

  if (tid < BM) {
    int i = m0 + tid;
    sRow[tid] = (i < ne) ? g_list[e * T_TOK + i] : -1;
  }
  __syncthreads();

  // ldmatrix per-lane offsets
  int arow = (lane & 7) + ((lane >> 3) & 1) * 8;
  int ak = (lane >> 4) * 8;
  int brow = (lane & 7) + (lane >> 4) * 8;
  int bk = ((lane >> 3) & 1) * 8;

  const float* w1b = w1 + ((size_t)e * HID + n0) * DIM;
  const float* w3b = w3 + ((size_t)e * HID + n0) * DIM;

  int r0 = tid >> 3, cv = tid & 7;

  float acc1[2][4][4], acc3[2][4][4];
#pragma unroll
  for (int a = 0; a < 2; a++)
#pragma unroll
    for (int b = 0; b < 4; b++)
#pragma unroll
      for (int c = 0; c < 4; c++) { acc1[a][b][c] = 0.f; acc3[a][b][c] = 0.f; }

  float4 rA[4], rB1[4], rB3[4];
#pragma unroll
  for (int j = 0; j < 4; j++) {
    int row = j * 16 + r0;
    int r = sRow[row];
    rA[j] = (r >= 0) ? *(const float4*)(x + (size_t)(r >> 1) * DIM + cv * 4)
                     : make_float4(0.f, 0.f, 0.f, 0.f);
    rB1[j] = *(const float4*)(w1b + (size_t)row * DIM + cv * 4);
    rB3[j] = *(const float4*)(w3b + (size_t)row * DIM + cv * 4);
  }

  for (int k0 = 0; k0 < DIM; k0 += BK) {
    __syncthreads();
#pragma unroll
    for (int j = 0; j < 4; j++) {
      int row = j * 16 + r0;
      uint2 hi, lo;
      split4(rA[j], hi, lo);
      *(uint2*)&sAh[row][cv * 4] = hi;
      *(uint2*)&sAl[row][cv * 4] = lo;
      split4(rB1[j], hi, lo);
      *(uint2*)&sB1h[row][cv * 4] = hi;
      *(uint2*)&sB1l[row][cv * 4] = lo;
      split4(rB3[j], hi, lo);
      *(uint2*)&sB3h[row][cv * 4] = hi;
      *(uint2*)&sB3l[row][cv * 4] = lo;
    }
    __syncthreads();

    int kn = k0 + BK;
    if (kn < DIM) {
#pragma unroll
      for (int j = 0; j < 4; j++) {
        int row = j * 16 + r0;
        int r = sRow[row];
        rA[j] = (r >= 0) ? *(const float4*)(x + (size_t)(r >> 1) * DIM + kn + cv * 4)
                         : make_float4(0.f, 0.f, 0.f, 0.f);
        rB1[j] = *(const float4*)(w1b + (size_t)row * DIM + kn + cv * 4);
        rB3[j] = *(const float4*)(w3b + (size_t)row * DIM + kn + cv * 4);
      }
    }

#pragma unroll
    for (int kc = 0; kc < BK; kc += 16) {
      uint32_t ah[2][4], al[2][4];
#pragma unroll
      for (int mf = 0; mf < 2; mf++) {
        ldsm4(ah[mf], &sAh[wm * 32 + mf * 16 + arow][kc + ak]);
        ldsm4(al[mf], &sAl[wm * 32 + mf * 16 + arow][kc + ak]);
      }
#pragma unroll
      for (int ng = 0; ng < 2; ng++) {
        int nb = wn * 32 + ng * 16 + brow;
        uint32_t b1h[4], b1l[4], b3h[4], b3l[4];
        ldsm4(b1h, &sB1h[nb][kc + bk]);
        ldsm4(b1l, &sB1l[nb][kc + bk]);
        ldsm4(b3h, &sB3h[nb][kc + bk]);
        ldsm4(b3l, &sB3l[nb][kc + bk]);
#pragma unroll
        for (int j2 = 0; j2 < 2; j2++) {
          int j = ng * 2 + j2;
#pragma unroll
          for (int mf = 0; mf < 2; mf++) {
            mma16816(acc1[mf][j], ah[mf], b1h[2 * j2], b1h[2 * j2 + 1]);
            mma16816(acc1[mf][j], al[mf], b1h[2 * j2], b1h[2 * j2 + 1]);
            mma16816(acc1[mf][j], ah[mf], b1l[2 * j2], b1l[2 * j2 + 1]);
            mma16816(acc3[mf][j], ah[mf], b3h[2 * j2], b3h[2 * j2 + 1]);
            mma16816(acc3[mf][j], al[mf], b3h[2 * j2], b3h[2 * j2 + 1]);
            mma16816(acc3[mf][j], ah[mf], b3l[2 * j2], b3l[2 * j2 + 1]);
          }
        }
      }
    }
  }

  // epilogue: h = silu(a1) * a3, split to bf16 hi/lo
  int gg = lane >> 2, q = lane & 3;
#pragma unroll
  for (int mf = 0; mf < 2; mf++) {
#pragma unroll
    for (int half = 0; half < 2; half++) {
      int rloc = wm * 32 + mf * 16 + gg + half * 8;
      int r = sRow[rloc];
      if (r < 0) continue;
      size_t base = (size_t)r * HID + n0 + wn * 32;
#pragma unroll
      for (int j = 0; j < 4; j++) {
        float a1 = acc1[mf][j][half * 2 + 0];
        float b1 = acc1[mf][j][half * 2 + 1];
        float a3 = acc3[mf][j][half * 2 + 0];
        float b3 = acc3[mf][j][half * 2 + 1];
        float h0 = (a1 / (1.f + expf(-a1))) * a3;
        float h1 = (b1 / (1.f + expf(-b1))) * b3;
        uint32_t hi, lo;
        split2(h0, h1, hi, lo);
        size_t off = base + j * 8 + 2 * q;
        *(uint32_t*)&g_hh[off] = hi;
        *(uint32_t*)&g_hl[off] = lo;
      }
    }
  }
}

// ---------------- FFN2: ye = h w2^T ----------------
__global__ __launch_bounds__(128, 3) void ffn2_kernel(const float* __restrict__ w2) {
  int e = blockIdx.z;
  int ne = g_cnt[e];
  int m0 = blockIdx.y * BM;
  if (m0 >= ne) return;
  int n0 = blockIdx.x * BN;

  __shared__ __align__(16) __nv_bfloat16 sAh[BM][BKP], sAl[BM][BKP];
  __shared__ __align__(16) __nv_bfloat16 sBh[BN][BKP], sBl[BN][BKP];
  __shared__ int sRow[BM];

  int tid = threadIdx.x;
  int lane = tid & 31, warp = tid >> 5;
  int wm = warp >> 1, wn = warp & 1;

  if (tid < BM) {
    int i = m0 + tid;
    sRow[tid] = (i < ne) ? g_list[e * T_TOK + i] : -1;
  }
  __syncthreads();

  int arow = (lane & 7) + ((lane >> 3) & 1) * 8;
  int ak = (lane >> 4) * 8;
  int brow = (lane & 7) + (lane >> 4) * 8;
  int bk = ((lane >> 3) & 1) * 8;

  const float* w2b = w2 + ((size_t)e * DIM + n0) * HID;

  // A staging (bf16 hi/lo direct copy): 2 chunks per array per thread
  int ar0 = tid >> 2, acv = tid & 3;
  // B staging (fp32 convert): 4 chunks per thread
  int br0 = tid >> 3, bcv = tid & 7;

  float acc[2][4][4];
#pragma unroll
  for (int a = 0; a < 2; a++)
#pragma unroll
    for (int b = 0; b < 4; b++)
#pragma unroll
      for (int c = 0; c < 4; c++) acc[a][b][c] = 0.f;

  uint4 rAh[2], rAl[2];
  float4 rB[4];
  const uint4 z4 = make_uint4(0u, 0u, 0u, 0u);
#pragma unroll
  for (int j = 0; j < 2; j++) {
    int row = j * 32 + ar0;
    int r = sRow[row];
    rAh[j] = (r >= 0) ? *(const uint4*)(g_hh + (size_t)r * HID + acv * 8) : z4;
    rAl[j] = (r >= 0) ? *(const uint4*)(g_hl + (size_t)r * HID + acv * 8) : z4;
  }
#pragma unroll
  for (int j = 0; j < 4; j++) {
    int row = j * 16 + br0;
    rB[j] = *(const float4*)(w2b + (size_t)row * HID + bcv * 4);
  }

  for (int k0 = 0; k0 < HID; k0 += BK) {
    __syncthreads();
#pragma unroll
    for (int j = 0; j < 2; j++) {
      int row = j * 32 + ar0;
      *(uint4*)&sAh[row][acv * 8] = rAh[j];
      *(uint4*)&sAl[row][acv * 8] = rAl[j];
    }
#pragma unroll
    for (int j = 0; j < 4; j++) {
      int row = j * 16 + br0;
      uint2 hi, lo;
      split4(rB[j], hi, lo);
      *(uint2*)&sBh[row][bcv * 4] = hi;
      *(uint2*)&sBl[row][bcv * 4] = lo;
    }
    __syncthreads();

    int kn = k0 + BK;
    if (kn < HID) {
#pragma unroll
      for (int j = 0; j < 2; j++) {
        int row = j * 32 + ar0;
        int r = sRow[row];
        rAh[j] = (r >= 0) ? *(const uint4*)(g_hh + (size_t)r * HID + kn + acv * 8) : z4;
        rAl[j] = (r >= 0) ? *(const uint4*)(g_hl + (size_t)r * HID + kn + acv * 8) : z4;
      }
#pragma unroll
      for (int j = 0; j < 4; j++) {
        int row = j * 16 + br0;
        rB[j] = *(const float4*)(w2b + (size_t)row * HID + kn + bcv * 4);
      }
    }

#pragma unroll
    for (int kc = 0; kc < BK; kc += 16) {
      uint32_t ah[2][4], al[2][4];
#pragma unroll
      for (int mf = 0; mf < 2; mf++) {
        ldsm4(ah[mf], &sAh[wm * 32 + mf * 16 + arow][kc + ak]);
        ldsm4(al[mf], &sAl[wm * 32 + mf * 16 + arow][kc + ak]);
      }
#pragma unroll
      for (int ng = 0; ng < 2; ng++) {
        int nb = wn * 32 + ng * 16 + brow;
        uint32_t bh[4], bl[4];
        ldsm4(bh, &sBh[nb][kc + bk]);
        ldsm4(bl, &sBl[nb][kc + bk]);
#pragma unroll
        for (int j2 = 0; j2 < 2; j2++) {
          int j = ng * 2 + j2;
#pragma unroll
          for (int mf = 0; mf < 2; mf++) {
            mma16816(acc[mf][j], ah[mf], bh[2 * j2], bh[2 * j2 + 1]);
            mma16816(acc[mf][j], al[mf], bh[2 * j2], bh[2 * j2 + 1]);
            mma16816(acc[mf][j], ah[mf], bl[2 * j2], bl[2 * j2 + 1]);
          }
        }
      }
    }
  }

  int gg = lane >> 2, q = lane & 3;
#pragma unroll
  for (int mf = 0; mf < 2; mf++) {
#pragma unroll
    for (int half = 0; half < 2; half++) {
      int rloc = wm * 32 + mf * 16 + gg + half * 8;
      int r = sRow[rloc];
      if (r < 0) continue;
      float* yrow = g_ye + (size_t)r * DIM + n0 + wn * 32;
#pragma unroll
      for (int j = 0; j < 4; j++) {
        *(float2*)(yrow + j * 8 + 2 * q) =
            make_float2(acc[mf][j][half * 2 + 0], acc[mf][j][half * 2 + 1]);
      }
    }
  }
}

__global__ void combine_kernel(float* __restrict__ out) {
  int idx = blockIdx.x * 256 + threadIdx.x;
  int t = idx >> 10;
  int d = idx & 1023;
  out[idx] = g_wpair[2 * t] * g_ye[(size_t)(2 * t) * DIM + d] +
             g_wpair[2 * t + 1] * g_ye[(size_t)(2 * t + 1) * DIM + d];
}

// ---------------- launch ----------------
extern "C" void kernel_launch(void* const* d_in, const int* in_sizes, int n_in,
                              void* d_out, int out_size) {
  const float* x = (const float*)d_in[0];
  const float* gw = (const float*)d_in[1];
  const float* w1 = (const float*)d_in[2];
  const float* w2 = (const float*)d_in[3];
  const float* w3 = (const float*)d_in[4];
  float* out = (float*)d_out;

  reset_kernel<<<1, 32>>>();
  gate_kernel<<<T_TOK / 4, 128>>>(x, gw);
  ffn1_kernel<<<dim3(HID / BN, T_TOK / BM, NE), 128>>>(x, w1, w3);
  ffn2_kernel<<<dim3(DIM / BN, T_TOK / BM, NE), 128>>>(w2);
  combine_kernel<<<(T_TOK * DIM) / 256, 256>>>(out);
}

// round 10
// speedup vs baseline: 1.6394x; 1.6394x over previous
#include <cuda_runtime.h>
#include <cuda_fp16.h>
#include <cstdint>
#include <math.h>

#define T_TOK 2048
#define DIM 1024
#define HID 4096
#define NE 8
#define MAXMT 40
#define SWZ(o) ((o) ^ (((o) >> 3) & 0x70))
#define STAGE 32768
#define SMEM_TOT (4 * STAGE)

// -------- scratch (device globals; no allocation allowed) --------
__device__ int g_cnt[NE], g_off[NE], g_ntile, g_tile_e[64];
__device__ int g_list[NE * T_TOK];
__device__ int g_slot[2 * T_TOK];
__device__ float g_wpair[2 * T_TOK];
__device__ __align__(256) __half g_w13[(size_t)NE * 2 * HID * DIM];  // 128MB, rows 2n=w1[n],2n+1=w3[n]
__device__ __align__(256) __half g_w2c[(size_t)NE * DIM * HID];      // 64MB
__device__ __align__(256) __half g_x16[(size_t)MAXMT * 128 * DIM];   // 10MB gathered+padded
__device__ __align__(256) __half g_h16[(size_t)MAXMT * 128 * HID];   // 40MB
__device__ __align__(256) float g_ye[(size_t)MAXMT * 128 * DIM];     // 20MB

// -------- helpers --------
__device__ __forceinline__ uint32_t s2u(const void* p) {
  uint32_t a;
  asm("{ .reg .u64 t; cvta.to.shared.u64 t, %1; cvt.u32.u64 %0, t; }" : "=r"(a) : "l"(p));
  return a;
}
__device__ __forceinline__ void cp16(uint32_t dst, const void* src) {
  asm volatile("cp.async.cg.shared.global [%0], [%1], 16;" ::"r"(dst), "l"(src));
}
__device__ __forceinline__ void cpcommit() { asm volatile("cp.async.commit_group;"); }
__device__ __forceinline__ void cpwait3() { asm volatile("cp.async.wait_group 3;"); }

__device__ __forceinline__ void ldsm4(uint32_t r[4], uint32_t a) {
  asm volatile("ldmatrix.sync.aligned.m8n8.x4.shared.b16 {%0,%1,%2,%3}, [%4];"
               : "=r"(r[0]), "=r"(r[1]), "=r"(r[2]), "=r"(r[3])
               : "r"(a));
}
__device__ __forceinline__ void mma_h(float c[4], const uint32_t a[4], uint32_t b0, uint32_t b1) {
  asm volatile(
      "mma.sync.aligned.m16n8k16.row.col.f32.f16.f16.f32 "
      "{%0,%1,%2,%3}, {%4,%5,%6,%7}, {%8,%9}, {%0,%1,%2,%3};"
      : "+f"(c[0]), "+f"(c[1]), "+f"(c[2]), "+f"(c[3])
      : "r"(a[0]), "r"(a[1]), "r"(a[2]), "r"(a[3]), "r"(b0), "r"(b1));
}
__device__ __forceinline__ uint32_t packh2(float lo, float hi) {
  uint32_t r;
  asm("cvt.rn.f16x2.f32 %0, %1, %2;" : "=r"(r) : "f"(hi), "f"(lo));
  return r;
}
__device__ __forceinline__ uint4 pack8h(const float* v) {
  return make_uint4(packh2(v[0], v[1]), packh2(v[2], v[3]), packh2(v[4], v[5]),
                    packh2(v[6], v[7]));
}

// -------- small kernels --------
__global__ void reset_kernel() {
  if (threadIdx.x < NE) g_cnt[threadIdx.x] = 0;
}

__global__ void gate_kernel(const float* __restrict__ x, const float* __restrict__ gw) {
  int t = blockIdx.x * 4 + (threadIdx.x >> 5);
  int lane = threadIdx.x & 31;
  float p[NE];
#pragma unroll
  for (int e = 0; e < NE; e++) p[e] = 0.f;
  const float* xr = x + (size_t)t * DIM;
  for (int j = lane; j < DIM; j += 32) {
    float xv = xr[j];
#pragma unroll
    for (int e = 0; e < NE; e++) p[e] += xv * gw[e * DIM + j];
  }
#pragma unroll
  for (int off = 16; off > 0; off >>= 1)
#pragma unroll
    for (int e = 0; e < NE; e++) p[e] += __shfl_xor_sync(0xffffffffu, p[e], off);
  if (lane == 0) {
    int i0 = 0;
    float v0 = p[0];
#pragma unroll
    for (int e = 1; e < NE; e++)
      if (p[e] > v0) { v0 = p[e]; i0 = e; }
    int i1 = -1;
    float v1 = -3.0e38f;
#pragma unroll
    for (int e = 0; e < NE; e++)
      if (e != i0 && p[e] > v1) { v1 = p[e]; i1 = e; }
    float e1 = expf(v1 - v0);
    float w0 = 1.f / (1.f + e1);
    int pos = atomicAdd(&g_cnt[i0], 1);
    g_list[i0 * T_TOK + pos] = t * 2;
    g_wpair[t * 2] = w0;
    pos = atomicAdd(&g_cnt[i1], 1);
    g_list[i1 * T_TOK + pos] = t * 2 + 1;
    g_wpair[t * 2 + 1] = 1.f - w0;
  }
}

__global__ void finalize_kernel() {
  if (threadIdx.x == 0) {
    int off = 0;
    for (int e = 0; e < NE; e++) {
      g_off[e] = off;
      int pc = (g_cnt[e] + 127) & ~127;
      for (int t = 0; t < (pc >> 7); t++) g_tile_e[(off >> 7) + t] = e;
      off += pc;
    }
    g_ntile = off >> 7;
  }
}

// w1/w3 -> fp16, rows interleaved: R=2n -> w1[n], R=2n+1 -> w3[n]
__global__ void w13pack_kernel(const float* __restrict__ w1, const float* __restrict__ w3) {
  int idx = blockIdx.x * 256 + threadIdx.x;
  int c = idx & 127, R = (idx >> 7) & 8191, e = idx >> 20;
  const float* src = ((R & 1) ? w3 : w1) + ((size_t)e * HID + (R >> 1)) * DIM + c * 8;
  float v[8];
  *(float4*)v = *(const float4*)src;
  *(float4*)(v + 4) = *(const float4*)(src + 4);
  *(uint4*)(g_w13 + ((size_t)e * 8192 + R) * DIM + c * 8) = pack8h(v);
}

__global__ void w2pack_kernel(const float* __restrict__ w2) {
  int idx = blockIdx.x * 256 + threadIdx.x;
  int c = idx & 511, r = (idx >> 9) & 1023, e = idx >> 19;
  const float* src = w2 + ((size_t)e * DIM + r) * HID + c * 8;
  float v[8];
  *(float4*)v = *(const float4*)src;
  *(float4*)(v + 4) = *(const float4*)(src + 4);
  *(uint4*)(g_w2c + ((size_t)e * DIM + r) * HID + c * 8) = pack8h(v);
}

// gather + pad token rows -> fp16
__global__ void xpack_kernel(const float* __restrict__ x) {
  int idx = blockIdx.x * 256 + threadIdx.x;
  int c = idx & 127, s = idx >> 7;
  int mt = s >> 7;
  if (mt >= g_ntile) return;
  int e = g_tile_e[mt];
  int li = s - g_off[e];
  int pair = (li < g_cnt[e]) ? g_list[e * T_TOK + li] : -1;
  if (c == 0 && pair >= 0) g_slot[pair] = s;
  float v[8] = {0.f, 0.f, 0.f, 0.f, 0.f, 0.f, 0.f, 0.f};
  if (pair >= 0) {
    const float* src = x + (size_t)(pair >> 1) * DIM + c * 8;
    *(float4*)v = *(const float4*)src;
    *(float4*)(v + 4) = *(const float4*)(src + 4);
  }
  *(uint4*)(g_x16 + (size_t)s * DIM + c * 8) = pack8h(v);
}

// -------- GEMM core: block 128m x 128n, BK=64, 256 thr, warp tile 64x32 --------
__device__ __forceinline__ void issue_stage(uint32_t sbase, const __half* gA, int ldA,
                                            const __half* gB, int ldB) {
  int tid = threadIdx.x;
#pragma unroll
  for (int it = 0; it < 4; it++) {
    int sidx = it * 256 + tid;
    int row = sidx >> 3, seg = sidx & 7;
    uint32_t off = SWZ(row * 128 + seg * 16);
    cp16(sbase + off, gA + (size_t)row * ldA + seg * 8);
    cp16(sbase + 16384 + off, gB + (size_t)row * ldB + seg * 8);
  }
}

__device__ __forceinline__ void compute_stage(uint32_t sA, uint32_t sB, float acc[4][4][4],
                                              int wm, int wn, int arow, int ak, int brow,
                                              int bk) {
#pragma unroll
  for (int kc = 0; kc < 64; kc += 16) {
    uint32_t a[4][4];
#pragma unroll
    for (int mf = 0; mf < 4; mf++)
      ldsm4(a[mf], sA + SWZ((wm * 64 + mf * 16 + arow) * 128 + (kc + ak) * 2));
#pragma unroll
    for (int ng = 0; ng < 2; ng++) {
      uint32_t b[4];
      ldsm4(b, sB + SWZ((wn * 32 + ng * 16 + brow) * 128 + (kc + bk) * 2));
#pragma unroll
      for (int j2 = 0; j2 < 2; j2++)
#pragma unroll
        for (int mf = 0; mf < 4; mf++)
          mma_h(acc[mf][ng * 2 + j2], a[mf], b[2 * j2], b[2 * j2 + 1]);
    }
  }
}

__device__ __forceinline__ void gemm_main(const __half* gA, int ldA, const __half* gB, int ldB,
                                          int NK, uint32_t smem, float acc[4][4][4], int wm,
                                          int wn, int arow, int ak, int brow, int bk) {
#pragma unroll
  for (int s = 0; s < 3; s++) {
    issue_stage(smem + s * STAGE, gA + s * 64, ldA, gB + s * 64, ldB);
    cpcommit();
  }
  for (int i = 0; i < NK; i++) {
    int j = i + 3;
    if (j < NK) issue_stage(smem + (j & 3) * STAGE, gA + j * 64, ldA, gB + j * 64, ldB);
    cpcommit();
    cpwait3();
    __syncthreads();
    compute_stage(smem + (i & 3) * STAGE, smem + (i & 3) * STAGE + 16384, acc, wm, wn, arow,
                  ak, brow, bk);
    __syncthreads();
  }
}

// -------- FFN1: D[128 x 128] = x_tile @ w13_tile^T, cols interleaved (w1, w3) --------
__global__ __launch_bounds__(256, 1) void ffn1_kernel() {
  int mt = blockIdx.y;
  if (mt >= g_ntile) return;
  int nt = blockIdx.x, e = g_tile_e[mt];
  extern __shared__ __align__(1024) char sm[];
  uint32_t smem = s2u(sm);
  int tid = threadIdx.x, lane = tid & 31, warp = tid >> 5;
  int wm = warp >> 2, wn = warp & 3;
  int arow = (lane & 7) + ((lane >> 3) & 1) * 8, ak = (lane >> 4) * 8;
  int brow = (lane & 7) + (lane >> 4) * 8, bk = ((lane >> 3) & 1) * 8;
  float acc[4][4][4];
#pragma unroll
  for (int a = 0; a < 4; a++)
#pragma unroll
    for (int b = 0; b < 4; b++)
#pragma unroll
      for (int c = 0; c < 4; c++) acc[a][b][c] = 0.f;

  const __half* gA = g_x16 + (size_t)mt * 128 * DIM;
  const __half* gB = g_w13 + ((size_t)e * 8192 + nt * 128) * DIM;
  gemm_main(gA, DIM, gB, DIM, DIM / 64, smem, acc, wm, wn, arow, ak, brow, bk);

  int gg = lane >> 2, q = lane & 3;
  __half* hb = g_h16 + (size_t)mt * 128 * HID + (size_t)nt * 64;
#pragma unroll
  for (int mf = 0; mf < 4; mf++)
#pragma unroll
    for (int f = 0; f < 4; f++)
#pragma unroll
      for (int half = 0; half < 2; half++) {
        int row = wm * 64 + mf * 16 + gg + half * 8;
        float a1 = acc[mf][f][half * 2 + 0];
        float a3 = acc[mf][f][half * 2 + 1];
        float h = (a1 / (1.f + expf(-a1))) * a3;
        int col = wn * 16 + (f >> 1) * 8 + (f & 1) * 4 + q;
        hb[(size_t)row * HID + col] = __float2half_rn(h);
      }
}

// -------- FFN2: ye[128 x 128] = h_tile @ w2_tile^T --------
__global__ __launch_bounds__(256, 1) void ffn2_kernel() {
  int mt = blockIdx.y;
  if (mt >= g_ntile) return;
  int nt = blockIdx.x, e = g_tile_e[mt];
  extern __shared__ __align__(1024) char sm[];
  uint32_t smem = s2u(sm);
  int tid = threadIdx.x, lane = tid & 31, warp = tid >> 5;
  int wm = warp >> 2, wn = warp & 3;
  int arow = (lane & 7) + ((lane >> 3) & 1) * 8, ak = (lane >> 4) * 8;
  int brow = (lane & 7) + (lane >> 4) * 8, bk = ((lane >> 3) & 1) * 8;
  float acc[4][4][4];
#pragma unroll
  for (int a = 0; a < 4; a++)
#pragma unroll
    for (int b = 0; b < 4; b++)
#pragma unroll
      for (int c = 0; c < 4; c++) acc[a][b][c] = 0.f;

  const __half* gA = g_h16 + (size_t)mt * 128 * HID;
  const __half* gB = g_w2c + ((size_t)e * DIM + nt * 128) * HID;
  gemm_main(gA, HID, gB, HID, HID / 64, smem, acc, wm, wn, arow, ak, brow, bk);

  int gg = lane >> 2, q = lane & 3;
#pragma unroll
  for (int mf = 0; mf < 4; mf++)
#pragma unroll
    for (int f = 0; f < 4; f++)
#pragma unroll
      for (int half = 0; half < 2; half++) {
        int row = wm * 64 + mf * 16 + gg + half * 8;
        int col = nt * 128 + wn * 32 + (f >> 1) * 16 + (f & 1) * 8 + 2 * q;
        *(float2*)(g_ye + (size_t)(mt * 128 + row) * DIM + col) =
            make_float2(acc[mf][f][half * 2 + 0], acc[mf][f][half * 2 + 1]);
      }
}

__global__ void combine_kernel(float* __restrict__ out) {
  int idx = blockIdx.x * 256 + threadIdx.x;
  int t = idx >> 10, d = idx & 1023;
  int s0 = g_slot[2 * t], s1 = g_slot[2 * t + 1];
  out[idx] = g_wpair[2 * t] * g_ye[(size_t)s0 * DIM + d] +
             g_wpair[2 * t + 1] * g_ye[(size_t)s1 * DIM + d];
}

// -------- launch --------
extern "C" void kernel_launch(void* const* d_in, const int* in_sizes, int n_in,
                              void* d_out, int out_size) {
  const float* x = (const float*)d_in[0];
  const float* gw = (const float*)d_in[1];
  const float* w1 = (const float*)d_in[2];
  const float* w2 = (const float*)d_in[3];
  const float* w3 = (const float*)d_in[4];
  float* out = (float*)d_out;

  cudaFuncSetAttribute(ffn1_kernel, cudaFuncAttributeMaxDynamicSharedMemorySize, SMEM_TOT);
  cudaFuncSetAttribute(ffn2_kernel, cudaFuncAttributeMaxDynamicSharedMemorySize, SMEM_TOT);

  reset_kernel<<<1, 32>>>();
  gate_kernel<<<T_TOK / 4, 128>>>(x, gw);
  finalize_kernel<<<1, 32>>>();
  w13pack_kernel<<<(NE * 8192 * 128) / 256, 256>>>(w1, w3);
  w2pack_kernel<<<(NE * 1024 * 512) / 256, 256>>>(w2);
  xpack_kernel<<<(MAXMT * 128 * 128) / 256, 256>>>(x);
  ffn1_kernel<<<dim3(64, MAXMT), 256, SMEM_TOT>>>();
  ffn2_kernel<<<dim3(8, MAXMT), 256, SMEM_TOT>>>();
  combine_kernel<<<(T_TOK * DIM) / 256, 256>>>(out);
}

// round 13
// speedup vs baseline: 2.6555x; 1.6198x over previous
#include <cuda_runtime.h>
#include <cuda_fp16.h>
#include <cstdint>
#include <math.h>

#define T_TOK 2048
#define DIM 1024
#define HID 4096
#define NE 8
#define MAXMT 40
#define SWZ(o) ((o) ^ (((o) >> 3) & 0x70))
#define STAGE 32768
#define SMEM_TOT (3 * STAGE)

// -------- scratch (device globals; no allocation allowed) --------
__device__ int g_cnt[NE], g_off[NE], g_ntile, g_tile_e[64];
__device__ int g_list[NE * T_TOK];
__device__ int g_slot[2 * T_TOK];
__device__ float g_wpair[2 * T_TOK];
__device__ __align__(256) __half g_w13[(size_t)NE * 2 * HID * DIM];  // 128MB
__device__ __align__(256) __half g_w2c[(size_t)NE * DIM * HID];      // 64MB
__device__ __align__(256) __half g_x16[(size_t)MAXMT * 128 * DIM];   // 10MB
__device__ __align__(256) __half g_h16[(size_t)MAXMT * 128 * HID];   // 40MB
__device__ __align__(256) float g_ye[(size_t)MAXMT * 128 * DIM];     // 20MB

// -------- helpers --------
__device__ __forceinline__ uint32_t s2u(const void* p) {
  uint32_t a;
  asm("{ .reg .u64 t; cvta.to.shared.u64 t, %1; cvt.u32.u64 %0, t; }" : "=r"(a) : "l"(p));
  return a;
}
__device__ __forceinline__ void cp16(uint32_t dst, const void* src) {
  asm volatile("cp.async.cg.shared.global [%0], [%1], 16;" ::"r"(dst), "l"(src));
}
__device__ __forceinline__ void cpcommit() { asm volatile("cp.async.commit_group;"); }
__device__ __forceinline__ void cpwait2() { asm volatile("cp.async.wait_group 2;"); }

__device__ __forceinline__ void ldsm4(uint32_t r[4], uint32_t a) {
  asm volatile("ldmatrix.sync.aligned.m8n8.x4.shared.b16 {%0,%1,%2,%3}, [%4];"
               : "=r"(r[0]), "=r"(r[1]), "=r"(r[2]), "=r"(r[3])
               : "r"(a));
}
__device__ __forceinline__ void mma_h(float c[4], const uint32_t a[4], uint32_t b0, uint32_t b1) {
  asm volatile(
      "mma.sync.aligned.m16n8k16.row.col.f32.f16.f16.f32 "
      "{%0,%1,%2,%3}, {%4,%5,%6,%7}, {%8,%9}, {%0,%1,%2,%3};"
      : "+f"(c[0]), "+f"(c[1]), "+f"(c[2]), "+f"(c[3])
      : "r"(a[0]), "r"(a[1]), "r"(a[2]), "r"(a[3]), "r"(b0), "r"(b1));
}
__device__ __forceinline__ uint32_t packh2(float lo, float hi) {
  uint32_t r;
  asm("cvt.rn.f16x2.f32 %0, %1, %2;" : "=r"(r) : "f"(hi), "f"(lo));
  return r;
}
__device__ __forceinline__ uint4 pack8h(const float* v) {
  return make_uint4(packh2(v[0], v[1]), packh2(v[2], v[3]), packh2(v[4], v[5]),
                    packh2(v[6], v[7]));
}

// -------- small kernels --------
__global__ void reset_kernel() {
  if (threadIdx.x < NE) g_cnt[threadIdx.x] = 0;
}

__global__ void gate_kernel(const float* __restrict__ x, const float* __restrict__ gw) {
  int t = blockIdx.x * 4 + (threadIdx.x >> 5);
  int lane = threadIdx.x & 31;
  float p[NE];
#pragma unroll
  for (int e = 0; e < NE; e++) p[e] = 0.f;
  const float* xr = x + (size_t)t * DIM;
  for (int j = lane; j < DIM; j += 32) {
    float xv = xr[j];
#pragma unroll
    for (int e = 0; e < NE; e++) p[e] += xv * gw[e * DIM + j];
  }
#pragma unroll
  for (int off = 16; off > 0; off >>= 1)
#pragma unroll
    for (int e = 0; e < NE; e++) p[e] += __shfl_xor_sync(0xffffffffu, p[e], off);
  if (lane == 0) {
    int i0 = 0;
    float v0 = p[0];
#pragma unroll
    for (int e = 1; e < NE; e++)
      if (p[e] > v0) { v0 = p[e]; i0 = e; }
    int i1 = -1;
    float v1 = -3.0e38f;
#pragma unroll
    for (int e = 0; e < NE; e++)
      if (e != i0 && p[e] > v1) { v1 = p[e]; i1 = e; }
    float e1 = expf(v1 - v0);
    float w0 = 1.f / (1.f + e1);
    int pos = atomicAdd(&g_cnt[i0], 1);
    g_list[i0 * T_TOK + pos] = t * 2;
    g_wpair[t * 2] = w0;
    pos = atomicAdd(&g_cnt[i1], 1);
    g_list[i1 * T_TOK + pos] = t * 2 + 1;
    g_wpair[t * 2 + 1] = 1.f - w0;
  }
}

__global__ void finalize_kernel() {
  if (threadIdx.x == 0) {
    int off = 0;
    for (int e = 0; e < NE; e++) {
      g_off[e] = off;
      int pc = (g_cnt[e] + 127) & ~127;
      for (int t = 0; t < (pc >> 7); t++) g_tile_e[(off >> 7) + t] = e;
      off += pc;
    }
    g_ntile = off >> 7;
  }
}

// w1/w3 -> fp16, rows interleaved: R=2n -> w1[n], R=2n+1 -> w3[n]
__global__ void w13pack_kernel(const float* __restrict__ w1, const float* __restrict__ w3) {
  int idx = blockIdx.x * 256 + threadIdx.x;
  int c = idx & 127, R = (idx >> 7) & 8191, e = idx >> 20;
  const float* src = ((R & 1) ? w3 : w1) + ((size_t)e * HID + (R >> 1)) * DIM + c * 8;
  float v[8];
  *(float4*)v = *(const float4*)src;
  *(float4*)(v + 4) = *(const float4*)(src + 4);
  *(uint4*)(g_w13 + ((size_t)e * 8192 + R) * DIM + c * 8) = pack8h(v);
}

__global__ void w2pack_kernel(const float* __restrict__ w2) {
  int idx = blockIdx.x * 256 + threadIdx.x;
  int c = idx & 511, r = (idx >> 9) & 1023, e = idx >> 19;
  const float* src = w2 + ((size_t)e * DIM + r) * HID + c * 8;
  float v[8];
  *(float4*)v = *(const float4*)src;
  *(float4*)(v + 4) = *(const float4*)(src + 4);
  *(uint4*)(g_w2c + ((size_t)e * DIM + r) * HID + c * 8) = pack8h(v);
}

// gather + pad token rows -> fp16
__global__ void xpack_kernel(const float* __restrict__ x) {
  int idx = blockIdx.x * 256 + threadIdx.x;
  int c = idx & 127, s = idx >> 7;
  int mt = s >> 7;
  if (mt >= g_ntile) return;
  int e = g_tile_e[mt];
  int li = s - g_off[e];
  int pair = (li < g_cnt[e]) ? g_list[e * T_TOK + li] : -1;
  if (c == 0 && pair >= 0) g_slot[pair] = s;
  float v[8] = {0.f, 0.f, 0.f, 0.f, 0.f, 0.f, 0.f, 0.f};
  if (pair >= 0) {
    const float* src = x + (size_t)(pair >> 1) * DIM + c * 8;
    *(float4*)v = *(const float4*)src;
    *(float4*)(v + 4) = *(const float4*)(src + 4);
  }
  *(uint4*)(g_x16 + (size_t)s * DIM + c * 8) = pack8h(v);
}

// -------- GEMM core: block 128m x 128n, BK=64, 256 thr, warp tile 64x32 --------
__device__ __forceinline__ void issue_stage(uint32_t sbase, const __half* gA, int ldA,
                                            const __half* gB, int ldB) {
  int tid = threadIdx.x;
#pragma unroll
  for (int it = 0; it < 4; it++) {
    int sidx = it * 256 + tid;
    int row = sidx >> 3, seg = sidx & 7;
    uint32_t off = SWZ(row * 128 + seg * 16);
    cp16(sbase + off, gA + (size_t)row * ldA + seg * 8);
    cp16(sbase + 16384 + off, gB + (size_t)row * ldB + seg * 8);
  }
}

__device__ __forceinline__ void compute_stage(uint32_t sA, uint32_t sB, float acc[4][4][4],
                                              int wm, int wn, int arow, int ak, int brow,
                                              int bk) {
#pragma unroll
  for (int kc = 0; kc < 64; kc += 16) {
    uint32_t a[4][4];
#pragma unroll
    for (int mf = 0; mf < 4; mf++)
      ldsm4(a[mf], sA + SWZ((wm * 64 + mf * 16 + arow) * 128 + (kc + ak) * 2));
#pragma unroll
    for (int ng = 0; ng < 2; ng++) {
      uint32_t b[4];
      ldsm4(b, sB + SWZ((wn * 32 + ng * 16 + brow) * 128 + (kc + bk) * 2));
#pragma unroll
      for (int j2 = 0; j2 < 2; j2++)
#pragma unroll
        for (int mf = 0; mf < 4; mf++)
          mma_h(acc[mf][ng * 2 + j2], a[mf], b[2 * j2], b[2 * j2 + 1]);
    }
  }
}

// 3-stage pipeline, 2 CTAs/SM. Buffer for stage i is freed at the post-compute
// sync of iter i, then refilled with stage i+3 (2-iteration latency cover).
__device__ __forceinline__ void gemm_main(const __half* gA, int ldA, const __half* gB, int ldB,
                                          int NK, uint32_t smem, float acc[4][4][4], int wm,
                                          int wn, int arow, int ak, int brow, int bk) {
#pragma unroll
  for (int s = 0; s < 3; s++) {
    issue_stage(smem + s * STAGE, gA + s * 64, ldA, gB + s * 64, ldB);
    cpcommit();
  }
  for (int i = 0; i < NK; i++) {
    cpwait2();
    __syncthreads();
    uint32_t sb = smem + (i % 3) * STAGE;
    compute_stage(sb, sb + 16384, acc, wm, wn, arow, ak, brow, bk);
    __syncthreads();
    int j = i + 3;
    if (j < NK) issue_stage(sb, gA + (size_t)j * 64, ldA, gB + (size_t)j * 64, ldB);
    cpcommit();
  }
}

// -------- FFN1: D[128 x 128] = x_tile @ w13_tile^T, cols interleaved (w1, w3) --------
__global__ __launch_bounds__(256, 2) void ffn1_kernel() {
  int mt = blockIdx.y;
  if (mt >= g_ntile) return;
  int nt = blockIdx.x, e = g_tile_e[mt];
  extern __shared__ __align__(1024) char sm[];
  uint32_t smem = s2u(sm);
  int tid = threadIdx.x, lane = tid & 31, warp = tid >> 5;
  int wm = warp >> 2, wn = warp & 3;
  int arow = (lane & 7) + ((lane >> 3) & 1) * 8, ak = (lane >> 4) * 8;
  int brow = (lane & 7) + (lane >> 4) * 8, bk = ((lane >> 3) & 1) * 8;
  float acc[4][4][4];
#pragma unroll
  for (int a = 0; a < 4; a++)
#pragma unroll
    for (int b = 0; b < 4; b++)
#pragma unroll
      for (int c = 0; c < 4; c++) acc[a][b][c] = 0.f;

  const __half* gA = g_x16 + (size_t)mt * 128 * DIM;
  const __half* gB = g_w13 + ((size_t)e * 8192 + nt * 128) * DIM;
  gemm_main(gA, DIM, gB, DIM, DIM / 64, smem, acc, wm, wn, arow, ak, brow, bk);

  int gg = lane >> 2, q = lane & 3;
  __half* hb = g_h16 + (size_t)mt * 128 * HID + (size_t)nt * 64;
#pragma unroll
  for (int mf = 0; mf < 4; mf++)
#pragma unroll
    for (int f = 0; f < 4; f++)
#pragma unroll
      for (int half = 0; half < 2; half++) {
        int row = wm * 64 + mf * 16 + gg + half * 8;
        float a1 = acc[mf][f][half * 2 + 0];
        float a3 = acc[mf][f][half * 2 + 1];
        float h = (a1 / (1.f + expf(-a1))) * a3;
        int col = wn * 16 + (f >> 1) * 8 + (f & 1) * 4 + q;
        hb[(size_t)row * HID + col] = __float2half_rn(h);
      }
}

// -------- FFN2: ye[128 x 128] = h_tile @ w2_tile^T --------
__global__ __launch_bounds__(256, 2) void ffn2_kernel() {
  int mt = blockIdx.y;
  if (mt >= g_ntile) return;
  int nt = blockIdx.x, e = g_tile_e[mt];
  extern __shared__ __align__(1024) char sm[];
  uint32_t smem = s2u(sm);
  int tid = threadIdx.x, lane = tid & 31, warp = tid >> 5;
  int wm = warp >> 2, wn = warp & 3;
  int arow = (lane & 7) + ((lane >> 3) & 1) * 8, ak = (lane >> 4) * 8;
  int brow = (lane & 7) + (lane >> 4) * 8, bk = ((lane >> 3) & 1) * 8;
  float acc[4][4][4];
#pragma unroll
  for (int a = 0; a < 4; a++)
#pragma unroll
    for (int b = 0; b < 4; b++)
#pragma unroll
      for (int c = 0; c < 4; c++) acc[a][b][c] = 0.f;

  const __half* gA = g_h16 + (size_t)mt * 128 * HID;
  const __half* gB = g_w2c + ((size_t)e * DIM + nt * 128) * HID;
  gemm_main(gA, HID, gB, HID, HID / 64, smem, acc, wm, wn, arow, ak, brow, bk);

  int gg = lane >> 2, q = lane & 3;
#pragma unroll
  for (int mf = 0; mf < 4; mf++)
#pragma unroll
    for (int f = 0; f < 4; f++)
#pragma unroll
      for (int half = 0; half < 2; half++) {
        int row = wm * 64 + mf * 16 + gg + half * 8;
        int col = nt * 128 + wn * 32 + (f >> 1) * 16 + (f & 1) * 8 + 2 * q;
        *(float2*)(g_ye + (size_t)(mt * 128 + row) * DIM + col) =
            make_float2(acc[mf][f][half * 2 + 0], acc[mf][f][half * 2 + 1]);
      }
}

__global__ void combine_kernel(float* __restrict__ out) {
  int idx = blockIdx.x * 256 + threadIdx.x;
  int t = idx >> 10, d = idx & 1023;
  int s0 = g_slot[2 * t], s1 = g_slot[2 * t + 1];
  out[idx] = g_wpair[2 * t] * g_ye[(size_t)s0 * DIM + d] +
             g_wpair[2 * t + 1] * g_ye[(size_t)s1 * DIM + d];
}

// -------- launch --------
extern "C" void kernel_launch(void* const* d_in, const int* in_sizes, int n_in,
                              void* d_out, int out_size) {
  const float* x = (const float*)d_in[0];
  const float* gw = (const float*)d_in[1];
  const float* w1 = (const float*)d_in[2];
  const float* w2 = (const float*)d_in[3];
  const float* w3 = (const float*)d_in[4];
  float* out = (float*)d_out;

  cudaFuncSetAttribute(ffn1_kernel, cudaFuncAttributeMaxDynamicSharedMemorySize, SMEM_TOT);
  cudaFuncSetAttribute(ffn2_kernel, cudaFuncAttributeMaxDynamicSharedMemorySize, SMEM_TOT);

  reset_kernel<<<1, 32>>>();
  gate_kernel<<<T_TOK / 4, 128>>>(x, gw);
  finalize_kernel<<<1, 32>>>();
  w13pack_kernel<<<(NE * 8192 * 128) / 256, 256>>>(w1, w3);
  w2pack_kernel<<<(NE * 1024 * 512) / 256, 256>>>(w2);
  xpack_kernel<<<(MAXMT * 128 * 128) / 256, 256>>>(x);
  ffn1_kernel<<<dim3(64, MAXMT), 256, SMEM_TOT>>>();
  ffn2_kernel<<<dim3(8, MAXMT), 256, SMEM_TOT>>>();
  combine_kernel<<<(T_TOK * DIM) / 256, 256>>>(out);
}